// round 4
// baseline (speedup 1.0000x reference)
#include <cuda_runtime.h>
#include <cstdint>

#define NB 4
#define NH 6
#define NN 1024
#define ND 64
#define NCH 384
#define NPLANES (NB*NH)            /* 24 */
#define PLANE_QV (NN*ND)           /* 65536 */
#define S_TOTAL  (25165824u)       /* B*H*N*N */

// ---------------- scratch (device globals; no allocs allowed) ----------------
__device__ float g_q[NPLANES*PLANE_QV];
__device__ float g_k[NPLANES*PLANE_QV];
__device__ float g_v[NPLANES*PLANE_QV];
__device__ float g_qk[(size_t)NPLANES*NN*NN];   // raw scores, later masked attn (in place)
__device__ float g_o[NB*NN*NCH];

// ---------------- threefry2x32-20 (host+device) ----------------
__host__ __device__ inline unsigned rotl32(unsigned x, int r){
#ifdef __CUDA_ARCH__
  return __funnelshift_l(x, x, r);
#else
  return (x << r) | (x >> (32 - r));
#endif
}

__host__ __device__ inline void threefry2x32(unsigned k0, unsigned k1,
                                             unsigned c0, unsigned c1,
                                             unsigned &o0, unsigned &o1){
  unsigned ks0 = k0, ks1 = k1, ks2 = k0 ^ k1 ^ 0x1BD11BDAu;
  unsigned x0 = c0 + ks0, x1 = c1 + ks1;
#define TF_RND(r) { x0 += x1; x1 = rotl32(x1, r); x1 ^= x0; }
  TF_RND(13) TF_RND(15) TF_RND(26) TF_RND(6)
  x0 += ks1; x1 += ks2 + 1u;
  TF_RND(17) TF_RND(29) TF_RND(16) TF_RND(24)
  x0 += ks2; x1 += ks0 + 2u;
  TF_RND(13) TF_RND(15) TF_RND(26) TF_RND(6)
  x0 += ks0; x1 += ks1 + 3u;
  TF_RND(17) TF_RND(29) TF_RND(16) TF_RND(24)
  x0 += ks1; x1 += ks2 + 4u;
  TF_RND(13) TF_RND(15) TF_RND(26) TF_RND(6)
  x0 += ks2; x1 += ks0 + 5u;
#undef TF_RND
  o0 = x0; o1 = x1;
}

__device__ __forceinline__ float gumbel_from_bits(unsigned bits){
  // JAX: u = bitcast((bits>>9)|0x3f800000) - 1; r = max(tiny, u*(1-tiny)+tiny); g = -log(-log(r))
  const float tiny = 1.17549435e-38f;
  float f = __uint_as_float((bits >> 9) | 0x3f800000u) - 1.0f;
  float r = fmaxf(tiny, f + tiny);
  return -__logf(-__logf(r));
}

// ---------------- GEMM helpers ----------------
#define OUTER4(av,bv,acc) \
  acc[0][0]=fmaf(av.x,bv.x,acc[0][0]); acc[0][1]=fmaf(av.x,bv.y,acc[0][1]); \
  acc[0][2]=fmaf(av.x,bv.z,acc[0][2]); acc[0][3]=fmaf(av.x,bv.w,acc[0][3]); \
  acc[1][0]=fmaf(av.y,bv.x,acc[1][0]); acc[1][1]=fmaf(av.y,bv.y,acc[1][1]); \
  acc[1][2]=fmaf(av.y,bv.z,acc[1][2]); acc[1][3]=fmaf(av.y,bv.w,acc[1][3]); \
  acc[2][0]=fmaf(av.z,bv.x,acc[2][0]); acc[2][1]=fmaf(av.z,bv.y,acc[2][1]); \
  acc[2][2]=fmaf(av.z,bv.z,acc[2][2]); acc[2][3]=fmaf(av.z,bv.w,acc[2][3]); \
  acc[3][0]=fmaf(av.w,bv.x,acc[3][0]); acc[3][1]=fmaf(av.w,bv.y,acc[3][1]); \
  acc[3][2]=fmaf(av.w,bv.z,acc[3][2]); acc[3][3]=fmaf(av.w,bv.w,acc[3][3]);

#define DOT4(d, av, bv) d = fmaf(av.x,bv.x, fmaf(av.y,bv.y, fmaf(av.z,bv.z, fmaf(av.w,bv.w, d))));

// ---------------- K1: qkv = x @ W + b, scattered to q/k/v [b,h,n,d] ----------------
__global__ __launch_bounds__(256) void k_qkv(const float* __restrict__ X,
                                             const float* __restrict__ W,
                                             const float* __restrict__ bias){
  __shared__ __align__(16) float sA[16][68];  // [k][m]
  __shared__ __align__(16) float sB[16][64];  // [k][n]
  const int tid = threadIdx.x;
  const int tx = tid & 15, ty = tid >> 4;
  const int n0 = blockIdx.x * 64;   // output col tile (0..1151)
  const int m0 = blockIdx.y * 64;   // row tile (0..4095)
  float acc[4][4] = {};
  const int lak = tid & 15;
  const int lam = (tid >> 4) * 4;
  const int lbn = tid & 63;
  const int lbk = (tid >> 6) * 4;
  for (int kb = 0; kb < 384; kb += 16){
    #pragma unroll
    for (int i=0;i<4;i++) sA[lak][lam+i] = X[(size_t)(m0+lam+i)*384 + kb + lak];
    #pragma unroll
    for (int i=0;i<4;i++) sB[lbk+i][lbn] = W[(size_t)(kb+lbk+i)*1152 + n0 + lbn];
    __syncthreads();
    #pragma unroll
    for (int kk=0;kk<16;kk++){
      float4 av = *(const float4*)&sA[kk][ty*4];
      float4 bv = *(const float4*)&sB[kk][tx*4];
      OUTER4(av,bv,acc)
    }
    __syncthreads();
  }
  const int s = n0 / 384;
  const int h = (n0 % 384) / 64;    // tile never crosses s or h boundary (64 | 384)
  float* dst = (s==0) ? g_q : (s==1) ? g_k : g_v;
  const float b0 = bias[n0 + tx*4 + 0];
  const float b1 = bias[n0 + tx*4 + 1];
  const float b2 = bias[n0 + tx*4 + 2];
  const float b3 = bias[n0 + tx*4 + 3];
  #pragma unroll
  for (int i=0;i<4;i++){
    int r = m0 + ty*4 + i;
    int b = r >> 10, n = r & 1023;
    float4 v = make_float4(acc[i][0]+b0, acc[i][1]+b1, acc[i][2]+b2, acc[i][3]+b3);
    *(float4*)&dst[(size_t)((b*NH + h)*NN + n)*ND + tx*4] = v;
  }
}

// ---------------- K2: per-plane scores qk[n,m] = q[n,:] . k[m,:] ----------------
__global__ __launch_bounds__(256) void k_scores(){
  __shared__ __align__(16) float sQ[64][68];
  __shared__ __align__(16) float sK[64][68];
  const int tid = threadIdx.x;
  const int tx = tid & 15, ty = tid >> 4;
  const int p  = blockIdx.z;
  const int n0 = blockIdx.y * 64;
  const int m0 = blockIdx.x * 64;
  const float* Q  = g_q + (size_t)p*PLANE_QV;
  const float* Kp = g_k + (size_t)p*PLANE_QV;
  #pragma unroll
  for (int it=0; it<4; it++){
    int v = tid + 256*it;
    int r = v >> 4, c = (v & 15) * 4;
    *(float4*)&sQ[r][c] = *(const float4*)&Q[(size_t)(n0+r)*64 + c];
    *(float4*)&sK[r][c] = *(const float4*)&Kp[(size_t)(m0+r)*64 + c];
  }
  __syncthreads();
  float acc[4][4] = {};
  #pragma unroll
  for (int kt=0; kt<16; kt++){
    float4 a0 = *(const float4*)&sQ[ty*4+0][kt*4];
    float4 a1 = *(const float4*)&sQ[ty*4+1][kt*4];
    float4 a2 = *(const float4*)&sQ[ty*4+2][kt*4];
    float4 a3 = *(const float4*)&sQ[ty*4+3][kt*4];
    float4 b0 = *(const float4*)&sK[tx*4+0][kt*4];
    float4 b1 = *(const float4*)&sK[tx*4+1][kt*4];
    float4 b2 = *(const float4*)&sK[tx*4+2][kt*4];
    float4 b3 = *(const float4*)&sK[tx*4+3][kt*4];
    DOT4(acc[0][0],a0,b0) DOT4(acc[0][1],a0,b1) DOT4(acc[0][2],a0,b2) DOT4(acc[0][3],a0,b3)
    DOT4(acc[1][0],a1,b0) DOT4(acc[1][1],a1,b1) DOT4(acc[1][2],a1,b2) DOT4(acc[1][3],a1,b3)
    DOT4(acc[2][0],a2,b0) DOT4(acc[2][1],a2,b1) DOT4(acc[2][2],a2,b2) DOT4(acc[2][3],a2,b3)
    DOT4(acc[3][0],a3,b0) DOT4(acc[3][1],a3,b1) DOT4(acc[3][2],a3,b2) DOT4(acc[3][3],a3,b3)
  }
  #pragma unroll
  for (int i=0;i<4;i++){
    size_t base = ((size_t)p<<20) + ((size_t)(n0+ty*4+i)<<10) + m0 + tx*4;
    *(float4*)&g_qk[base] = make_float4(acc[i][0],acc[i][1],acc[i][2],acc[i][3]);
  }
}

// ---------------- K3: softmax(qk * 0.125) per row -> attn_mean output ----------------
__global__ __launch_bounds__(256) void k_softmax(float* __restrict__ am){
  __shared__ float red[8];
  const int row = blockIdx.x;                 // p*1024 + n
  const float* src = g_qk + ((size_t)row << 10);
  float* dst = am + ((size_t)row << 10);
  const int tid = threadIdx.x;
  float x[4];
  #pragma unroll
  for (int j=0;j<4;j++) x[j] = src[tid + 256*j] * 0.125f;
  float m = fmaxf(fmaxf(x[0],x[1]), fmaxf(x[2],x[3]));
  #pragma unroll
  for (int o=16;o>0;o>>=1) m = fmaxf(m, __shfl_xor_sync(0xffffffffu, m, o));
  if ((tid & 31) == 0) red[tid>>5] = m;
  __syncthreads();
  if (tid == 0){
    float mm = red[0];
    #pragma unroll
    for (int i=1;i<8;i++) mm = fmaxf(mm, red[i]);
    red[0] = mm;
  }
  __syncthreads();
  m = red[0];
  __syncthreads();
  float e[4]; float s = 0.f;
  #pragma unroll
  for (int j=0;j<4;j++){ e[j] = expf(x[j]-m); s += e[j]; }
  #pragma unroll
  for (int o=16;o>0;o>>=1) s += __shfl_xor_sync(0xffffffffu, s, o);
  if ((tid & 31) == 0) red[tid>>5] = s;
  __syncthreads();
  if (tid == 0){
    float ss = red[0];
    #pragma unroll
    for (int i=1;i<8;i++) ss += red[i];
    red[0] = ss;
  }
  __syncthreads();
  s = red[0];
  #pragma unroll
  for (int j=0;j<4;j++) dst[tid + 256*j] = e[j] / s;
}

// ---------------- K4: conv+tanh -> u output; gumbel mask (partitionable threefry);
//                     masked attn written in-place into g_qk ----------------
__global__ __launch_bounds__(256) void k_mix(const float* __restrict__ cw,
                                             const float* __restrict__ cb,
                                             const float* __restrict__ am,
                                             float* __restrict__ u_out,
                                             unsigned k0a, unsigned k0b,
                                             unsigned k1a, unsigned k1b){
  __shared__ float scw[36];
  __shared__ float scb[6];
  const int tid = threadIdx.x;
  if (tid < 36) scw[tid] = cw[tid];
  if (tid < 6)  scb[tid] = cb[tid];
  __syncthreads();
  const int m = blockIdx.x*256 + tid;
  const int n = blockIdx.y;
  const int b = blockIdx.z;            // 0..3
  float qv[6];
  #pragma unroll
  for (int h=0;h<6;h++)
    qv[h] = g_qk[((size_t)((b*6+h)*NN + n) << 10) + m];
  #pragma unroll
  for (int o=0;o<6;o++){
    float t = scb[o];
    #pragma unroll
    for (int h=0;h<6;h++) t = fmaf(scw[o*6+h], qv[h], t);
    float u = (tanhf(t) + 1.0f) * 0.5f;     // log(exp(t)) == t to 1 ulp
    unsigned idx = ((unsigned)(b*6+o) << 20) | ((unsigned)n << 10) | (unsigned)m;
    u_out[idx] = u;
    // JAX partitionable threefry: per-element counter (hi=0, lo=idx); 32-bit bits = lane0 ^ lane1
    unsigned a0,a1,b0,b1;
    threefry2x32(k0a,k0b, 0u, idx, a0,a1);
    threefry2x32(k1a,k1b, 0u, idx, b0,b1);
    float g0 = gumbel_from_bits(a0 ^ a1);
    float g1 = gumbel_from_bits(b0 ^ b1);
    bool hard = ((1.0f - u) + g1) > (u + g0);
    g_qk[idx] = hard ? am[idx] : 0.0f;
  }
}

// ---------------- K5: per-plane out = masked_attn @ v  -> g_o [b,n,h*64+d] ----------------
__global__ __launch_bounds__(256) void k_attnv(){
  __shared__ __align__(16) float sA[64][68];   // [n][m]
  __shared__ __align__(16) float sV[64][68];   // [m][d]
  const int tid = threadIdx.x;
  const int tx = tid & 15, ty = tid >> 4;
  const int n0 = blockIdx.x * 64;
  const int p  = blockIdx.y;
  const float* Ap = g_qk + ((size_t)p << 20);
  const float* Vp = g_v + (size_t)p*PLANE_QV;
  float4 acc[4];
  #pragma unroll
  for (int i=0;i<4;i++) acc[i] = make_float4(0.f,0.f,0.f,0.f);
  for (int mb=0; mb<1024; mb+=64){
    #pragma unroll
    for (int it=0; it<4; it++){
      int v = tid + 256*it;
      int r = v >> 4, c = (v & 15) * 4;
      *(float4*)&sA[r][c] = *(const float4*)&Ap[((size_t)(n0+r)<<10) + mb + c];
      *(float4*)&sV[r][c] = *(const float4*)&Vp[(size_t)(mb+r)*64 + c];
    }
    __syncthreads();
    #pragma unroll 8
    for (int kk=0;kk<64;kk++){
      float4 vv = *(const float4*)&sV[kk][tx*4];
      float a0 = sA[ty*4+0][kk];
      float a1 = sA[ty*4+1][kk];
      float a2 = sA[ty*4+2][kk];
      float a3 = sA[ty*4+3][kk];
      acc[0].x=fmaf(a0,vv.x,acc[0].x); acc[0].y=fmaf(a0,vv.y,acc[0].y); acc[0].z=fmaf(a0,vv.z,acc[0].z); acc[0].w=fmaf(a0,vv.w,acc[0].w);
      acc[1].x=fmaf(a1,vv.x,acc[1].x); acc[1].y=fmaf(a1,vv.y,acc[1].y); acc[1].z=fmaf(a1,vv.z,acc[1].z); acc[1].w=fmaf(a1,vv.w,acc[1].w);
      acc[2].x=fmaf(a2,vv.x,acc[2].x); acc[2].y=fmaf(a2,vv.y,acc[2].y); acc[2].z=fmaf(a2,vv.z,acc[2].z); acc[2].w=fmaf(a2,vv.w,acc[2].w);
      acc[3].x=fmaf(a3,vv.x,acc[3].x); acc[3].y=fmaf(a3,vv.y,acc[3].y); acc[3].z=fmaf(a3,vv.z,acc[3].z); acc[3].w=fmaf(a3,vv.w,acc[3].w);
    }
    __syncthreads();
  }
  const int b = p / 6, h = p % 6;
  #pragma unroll
  for (int i=0;i<4;i++){
    int r = n0 + ty*4 + i;
    *(float4*)&g_o[(size_t)(b*NN + r)*NCH + h*64 + tx*4] = acc[i];
  }
}

// ---------------- K6: out = g_o @ proj_w + proj_b ----------------
__global__ __launch_bounds__(256) void k_proj(const float* __restrict__ W,
                                              const float* __restrict__ bias,
                                              float* __restrict__ out){
  __shared__ __align__(16) float sA[16][68];
  __shared__ __align__(16) float sB[16][64];
  const int tid = threadIdx.x;
  const int tx = tid & 15, ty = tid >> 4;
  const int n0 = blockIdx.x * 64;
  const int m0 = blockIdx.y * 64;
  float acc[4][4] = {};
  const int lak = tid & 15;
  const int lam = (tid >> 4) * 4;
  const int lbn = tid & 63;
  const int lbk = (tid >> 6) * 4;
  for (int kb = 0; kb < 384; kb += 16){
    #pragma unroll
    for (int i=0;i<4;i++) sA[lak][lam+i] = g_o[(size_t)(m0+lam+i)*384 + kb + lak];
    #pragma unroll
    for (int i=0;i<4;i++) sB[lbk+i][lbn] = W[(size_t)(kb+lbk+i)*384 + n0 + lbn];
    __syncthreads();
    #pragma unroll
    for (int kk=0;kk<16;kk++){
      float4 av = *(const float4*)&sA[kk][ty*4];
      float4 bv = *(const float4*)&sB[kk][tx*4];
      OUTER4(av,bv,acc)
    }
    __syncthreads();
  }
  const float b0 = bias[n0 + tx*4 + 0];
  const float b1 = bias[n0 + tx*4 + 1];
  const float b2 = bias[n0 + tx*4 + 2];
  const float b3 = bias[n0 + tx*4 + 3];
  #pragma unroll
  for (int i=0;i<4;i++){
    int r = m0 + ty*4 + i;
    float4 v = make_float4(acc[i][0]+b0, acc[i][1]+b1, acc[i][2]+b2, acc[i][3]+b3);
    *(float4*)&out[(size_t)r*384 + n0 + tx*4] = v;
  }
}

// ---------------- launch ----------------
extern "C" void kernel_launch(void* const* d_in, const int* in_sizes, int n_in,
                              void* d_out, int out_size){
  (void)in_sizes; (void)n_in; (void)out_size;
  const float* x      = (const float*)d_in[0];
  const float* qkv_w  = (const float*)d_in[1];
  const float* qkv_b  = (const float*)d_in[2];
  const float* proj_w = (const float*)d_in[3];
  const float* proj_b = (const float*)d_in[4];
  const float* conv_w = (const float*)d_in[5];
  const float* conv_b = (const float*)d_in[6];
  float* out      = (float*)d_out;
  float* out_attn = out + (size_t)NB*NN*NCH;          // 1,572,864
  float* out_u    = out_attn + (size_t)S_TOTAL;       // +25,165,824

  // JAX key derivation: gk = key(42) -> raw (0,42); fold_in(gk,i) = threefry(gk, (0,i))
  unsigned k0a,k0b,k1a,k1b;
  threefry2x32(0u, 42u, 0u, 0u, k0a, k0b);
  threefry2x32(0u, 42u, 0u, 1u, k1a, k1b);

  k_qkv   <<<dim3(18,64), 256>>>(x, qkv_w, qkv_b);
  k_scores<<<dim3(16,16,24), 256>>>();
  k_softmax<<<24576, 256>>>(out_attn);
  k_mix   <<<dim3(4,1024,4), 256>>>(conv_w, conv_b, out_attn, out_u, k0a,k0b,k1a,k1b);
  k_attnv <<<dim3(16,24), 256>>>();
  k_proj  <<<dim3(6,64), 256>>>(proj_w, proj_b, out);
}

// round 6
// speedup vs baseline: 1.4283x; 1.4283x over previous
#include <cuda_runtime.h>
#include <cuda_bf16.h>
#include <cstdint>

#define NB 4
#define NH 6
#define NN 1024
#define ND 64
#define NCH 384
#define NPLANES (NB*NH)            /* 24 */
#define PLANE_QV (NN*ND)           /* 65536 */
#define S_TOTAL  (25165824u)       /* B*H*N*N */

// ---------------- scratch (device globals; no allocs allowed) ----------------
__device__ __nv_bfloat16 g_qh[NPLANES*PLANE_QV];   // q hi  [p][n][d]
__device__ __nv_bfloat16 g_ql[NPLANES*PLANE_QV];   // q lo
__device__ __nv_bfloat16 g_kh[NPLANES*PLANE_QV];   // k hi  [p][m][d]
__device__ __nv_bfloat16 g_kl[NPLANES*PLANE_QV];
__device__ __nv_bfloat16 g_vh[NPLANES*PLANE_QV];   // v hi  [p][d][n]  (TRANSPOSED)
__device__ __nv_bfloat16 g_vl[NPLANES*PLANE_QV];
__device__ float g_qk[(size_t)NPLANES*NN*NN];      // raw scores f32
__device__ __nv_bfloat16 g_ah[(size_t)NPLANES*NN*NN];  // masked attn hi [p][n][m]
__device__ __nv_bfloat16 g_al[(size_t)NPLANES*NN*NN];  // masked attn lo
__device__ float g_o[NB*NN*NCH];

// ---------------- threefry2x32-20 (host+device) ----------------
__host__ __device__ inline unsigned rotl32(unsigned x, int r){
#ifdef __CUDA_ARCH__
  return __funnelshift_l(x, x, r);
#else
  return (x << r) | (x >> (32 - r));
#endif
}

__host__ __device__ inline void threefry2x32(unsigned k0, unsigned k1,
                                             unsigned c0, unsigned c1,
                                             unsigned &o0, unsigned &o1){
  unsigned ks0 = k0, ks1 = k1, ks2 = k0 ^ k1 ^ 0x1BD11BDAu;
  unsigned x0 = c0 + ks0, x1 = c1 + ks1;
#define TF_RND(r) { x0 += x1; x1 = rotl32(x1, r); x1 ^= x0; }
  TF_RND(13) TF_RND(15) TF_RND(26) TF_RND(6)
  x0 += ks1; x1 += ks2 + 1u;
  TF_RND(17) TF_RND(29) TF_RND(16) TF_RND(24)
  x0 += ks2; x1 += ks0 + 2u;
  TF_RND(13) TF_RND(15) TF_RND(26) TF_RND(6)
  x0 += ks0; x1 += ks1 + 3u;
  TF_RND(17) TF_RND(29) TF_RND(16) TF_RND(24)
  x0 += ks1; x1 += ks2 + 4u;
  TF_RND(13) TF_RND(15) TF_RND(26) TF_RND(6)
  x0 += ks2; x1 += ks0 + 5u;
#undef TF_RND
  o0 = x0; o1 = x1;
}

__device__ __forceinline__ float gumbel_from_bits(unsigned bits){
  const float tiny = 1.17549435e-38f;
  float f = __uint_as_float((bits >> 9) | 0x3f800000u) - 1.0f;
  float r = fmaxf(tiny, f + tiny);
  return -__logf(-__logf(r));
}

// ---------------- bf16 split + mma helpers ----------------
__device__ __forceinline__ void f2bf(float x, __nv_bfloat16 &h, __nv_bfloat16 &l){
  h = __float2bfloat16(x);
  l = __float2bfloat16(x - __bfloat162float(h));
}

__device__ __forceinline__ uint32_t sptr(const void* p){
  return (uint32_t)__cvta_generic_to_shared(p);
}

__device__ __forceinline__ void ldm_x4(uint32_t a, uint32_t &r0, uint32_t &r1,
                                       uint32_t &r2, uint32_t &r3){
  asm volatile("ldmatrix.sync.aligned.m8n8.x4.shared.b16 {%0,%1,%2,%3}, [%4];"
    : "=r"(r0),"=r"(r1),"=r"(r2),"=r"(r3) : "r"(a));
}
__device__ __forceinline__ void ldm_x2(uint32_t a, uint32_t &r0, uint32_t &r1){
  asm volatile("ldmatrix.sync.aligned.m8n8.x2.shared.b16 {%0,%1}, [%2];"
    : "=r"(r0),"=r"(r1) : "r"(a));
}
__device__ __forceinline__ void mma16816(float &c0,float &c1,float &c2,float &c3,
    uint32_t a0,uint32_t a1,uint32_t a2,uint32_t a3, uint32_t b0,uint32_t b1){
  asm volatile("mma.sync.aligned.m16n8k16.row.col.f32.bf16.bf16.f32 "
    "{%0,%1,%2,%3}, {%4,%5,%6,%7}, {%8,%9}, {%0,%1,%2,%3};"
    : "+f"(c0),"+f"(c1),"+f"(c2),"+f"(c3)
    : "r"(a0),"r"(a1),"r"(a2),"r"(a3),"r"(b0),"r"(b1));
}

#define OUTER4(av,bv,acc) \
  acc[0][0]=fmaf(av.x,bv.x,acc[0][0]); acc[0][1]=fmaf(av.x,bv.y,acc[0][1]); \
  acc[0][2]=fmaf(av.x,bv.z,acc[0][2]); acc[0][3]=fmaf(av.x,bv.w,acc[0][3]); \
  acc[1][0]=fmaf(av.y,bv.x,acc[1][0]); acc[1][1]=fmaf(av.y,bv.y,acc[1][1]); \
  acc[1][2]=fmaf(av.y,bv.z,acc[1][2]); acc[1][3]=fmaf(av.y,bv.w,acc[1][3]); \
  acc[2][0]=fmaf(av.z,bv.x,acc[2][0]); acc[2][1]=fmaf(av.z,bv.y,acc[2][1]); \
  acc[2][2]=fmaf(av.z,bv.z,acc[2][2]); acc[2][3]=fmaf(av.z,bv.w,acc[2][3]); \
  acc[3][0]=fmaf(av.w,bv.x,acc[3][0]); acc[3][1]=fmaf(av.w,bv.y,acc[3][1]); \
  acc[3][2]=fmaf(av.w,bv.z,acc[3][2]); acc[3][3]=fmaf(av.w,bv.w,acc[3][3]);

// ---------------- K1: qkv = x @ W + b -> bf16 hi/lo scratch (v transposed) ----------------
__global__ __launch_bounds__(256) void k_qkv(const float* __restrict__ X,
                                             const float* __restrict__ W,
                                             const float* __restrict__ bias){
  __shared__ __align__(16) float sA[16][68];  // [k][m]
  __shared__ __align__(16) float sB[16][64];  // [k][n]
  __shared__ __align__(16) float sT[64][65];  // v transpose staging [d][token]
  const int tid = threadIdx.x;
  const int tx = tid & 15, ty = tid >> 4;
  const int n0 = blockIdx.x * 64;   // output col tile (0..1151)
  const int m0 = blockIdx.y * 64;   // row tile (0..4095)
  float acc[4][4] = {};
  const int lak = tid & 15;
  const int lam = (tid >> 4) * 4;
  const int lbn = tid & 63;
  const int lbk = (tid >> 6) * 4;
  for (int kb = 0; kb < 384; kb += 16){
    #pragma unroll
    for (int i=0;i<4;i++) sA[lak][lam+i] = X[(size_t)(m0+lam+i)*384 + kb + lak];
    #pragma unroll
    for (int i=0;i<4;i++) sB[lbk+i][lbn] = W[(size_t)(kb+lbk+i)*1152 + n0 + lbn];
    __syncthreads();
    #pragma unroll
    for (int kk=0;kk<16;kk++){
      float4 av = *(const float4*)&sA[kk][ty*4];
      float4 bv = *(const float4*)&sB[kk][tx*4];
      OUTER4(av,bv,acc)
    }
    __syncthreads();
  }
  const int s = n0 / 384;
  const int h = (n0 % 384) / 64;
  const float bs[4] = { bias[n0+tx*4+0], bias[n0+tx*4+1], bias[n0+tx*4+2], bias[n0+tx*4+3] };
  if (s < 2){
    __nv_bfloat16* dh = s ? g_kh : g_qh;
    __nv_bfloat16* dl = s ? g_kl : g_ql;
    #pragma unroll
    for (int i=0;i<4;i++){
      int r = m0 + ty*4 + i;
      int bb = r >> 10, nn = r & 1023;
      size_t base = ((size_t)(bb*NH + h)*NN + nn)*ND + tx*4;
      union { __nv_bfloat16 q[4]; uint2 u; } ph, pl;
      #pragma unroll
      for (int j=0;j<4;j++) f2bf(acc[i][j]+bs[j], ph.q[j], pl.q[j]);
      *(uint2*)&dh[base] = ph.u;
      *(uint2*)&dl[base] = pl.u;
    }
  } else {
    // v: transpose through smem, store [p][d][n]
    #pragma unroll
    for (int i=0;i<4;i++)
      #pragma unroll
      for (int j=0;j<4;j++)
        sT[tx*4+j][ty*4+i] = acc[i][j] + bs[j];
    __syncthreads();
    const int dloc = tid >> 2;
    const int nch  = (tid & 3) * 16;
    const int bb = m0 >> 10;
    const int nb = (m0 & 1023) + nch;
    size_t base = ((size_t)(bb*NH + h))*PLANE_QV + (size_t)dloc*NN + nb;
    union { __nv_bfloat16 q[16]; uint4 u[2]; } ph, pl;
    #pragma unroll
    for (int kk=0;kk<16;kk++) f2bf(sT[dloc][nch+kk], ph.q[kk], pl.q[kk]);
    *(uint4*)&g_vh[base]   = ph.u[0];
    *(uint4*)&g_vh[base+8] = ph.u[1];
    *(uint4*)&g_vl[base]   = pl.u[0];
    *(uint4*)&g_vl[base+8] = pl.u[1];
  }
}

// ---------------- K2: scores via mma.sync bf16 split ----------------
#define SQS 72
__global__ __launch_bounds__(256) void k_scores_mma(){
  __shared__ __align__(16) __nv_bfloat16 sQh[64*SQS], sQl[64*SQS];
  __shared__ __align__(16) __nv_bfloat16 sKh[64*SQS], sKl[64*SQS];
  const int tid = threadIdx.x;
  const int p = blockIdx.z, n0 = blockIdx.y*64, m0 = blockIdx.x*64;
  const __nv_bfloat16* Qh = g_qh + (size_t)p*PLANE_QV + (size_t)n0*ND;
  const __nv_bfloat16* Ql = g_ql + (size_t)p*PLANE_QV + (size_t)n0*ND;
  const __nv_bfloat16* Kh = g_kh + (size_t)p*PLANE_QV + (size_t)m0*ND;
  const __nv_bfloat16* Kl = g_kl + (size_t)p*PLANE_QV + (size_t)m0*ND;
  #pragma unroll
  for (int c0=0;c0<2;c0++){
    int c = tid + 256*c0;
    int row = c >> 3, col = (c & 7) * 8;
    *(uint4*)&sQh[row*SQS+col] = *(const uint4*)&Qh[row*64+col];
    *(uint4*)&sQl[row*SQS+col] = *(const uint4*)&Ql[row*64+col];
    *(uint4*)&sKh[row*SQS+col] = *(const uint4*)&Kh[row*64+col];
    *(uint4*)&sKl[row*SQS+col] = *(const uint4*)&Kl[row*64+col];
  }
  __syncthreads();
  const int w = tid >> 5, lane = tid & 31;
  const int ns = (w >> 1) * 16, mh = (w & 1) * 32;
  float acc[4][4] = {};
  #pragma unroll
  for (int ks=0; ks<4; ks++){
    const int k0 = ks*16;
    const int arow = ns + (lane & 15);
    const int acol = k0 + (lane >> 4) * 8;
    uint32_t ah0,ah1,ah2,ah3, al0,al1,al2,al3;
    ldm_x4(sptr(&sQh[arow*SQS + acol]), ah0,ah1,ah2,ah3);
    ldm_x4(sptr(&sQl[arow*SQS + acol]), al0,al1,al2,al3);
    const int bro = (lane & 7);
    const int bco = k0 + ((lane >> 3) & 1) * 8;
    #pragma unroll
    for (int t=0;t<4;t++){
      const int brow = mh + t*8 + bro;
      uint32_t bh0,bh1, bl0,bl1;
      ldm_x2(sptr(&sKh[brow*SQS + bco]), bh0,bh1);
      ldm_x2(sptr(&sKl[brow*SQS + bco]), bl0,bl1);
      mma16816(acc[t][0],acc[t][1],acc[t][2],acc[t][3], ah0,ah1,ah2,ah3, bh0,bh1);
      mma16816(acc[t][0],acc[t][1],acc[t][2],acc[t][3], ah0,ah1,ah2,ah3, bl0,bl1);
      mma16816(acc[t][0],acc[t][1],acc[t][2],acc[t][3], al0,al1,al2,al3, bh0,bh1);
    }
  }
  const int crow = n0 + ns + (lane >> 2);
  #pragma unroll
  for (int t=0;t<4;t++){
    const int ccol = m0 + mh + t*8 + (lane & 3)*2;
    size_t base = ((size_t)p<<20) + ((size_t)crow<<10) + ccol;
    *(float2*)&g_qk[base]            = make_float2(acc[t][0], acc[t][1]);
    *(float2*)&g_qk[base + (8<<10)]  = make_float2(acc[t][2], acc[t][3]);
  }
}

// ---------------- K3: fused softmax + conv/tanh + gumbel mask ----------------
__global__ __launch_bounds__(256) void k_smix(const float* __restrict__ cw,
                                              const float* __restrict__ cb,
                                              float* __restrict__ am_out,
                                              float* __restrict__ u_out,
                                              unsigned k0a, unsigned k0b,
                                              unsigned k1a, unsigned k1b){
  __shared__ float scw[36];
  __shared__ float scb[6];
  __shared__ float red[6][8];
  __shared__ float bcast[6];
  const int tid = threadIdx.x;
  const int wid = tid >> 5, lane = tid & 31;
  if (tid < 36) scw[tid] = cw[tid];
  if (tid < 6)  scb[tid] = cb[tid];
  const int n = blockIdx.x;
  const int b = blockIdx.y;
  float qv[6][4];
  #pragma unroll
  for (int h=0;h<6;h++){
    size_t base = ((size_t)(b*6+h) << 20) + ((size_t)n << 10) + tid;
    #pragma unroll
    for (int j=0;j<4;j++) qv[h][j] = g_qk[base + 256*j];
  }
  // row max per head (raw units)
  #pragma unroll
  for (int h=0;h<6;h++){
    float lm = fmaxf(fmaxf(qv[h][0],qv[h][1]), fmaxf(qv[h][2],qv[h][3]));
    #pragma unroll
    for (int o=16;o>0;o>>=1) lm = fmaxf(lm, __shfl_xor_sync(0xffffffffu, lm, o));
    if (lane == 0) red[h][wid] = lm;
  }
  __syncthreads();
  if (tid < 6){
    float mm = red[tid][0];
    #pragma unroll
    for (int i=1;i<8;i++) mm = fmaxf(mm, red[tid][i]);
    bcast[tid] = mm;
  }
  __syncthreads();
  float at[6][4];
  #pragma unroll
  for (int h=0;h<6;h++){
    float mr = bcast[h];
    float s = 0.f;
    #pragma unroll
    for (int j=0;j<4;j++){ at[h][j] = expf((qv[h][j]-mr)*0.125f); s += at[h][j]; }
    #pragma unroll
    for (int o=16;o>0;o>>=1) s += __shfl_xor_sync(0xffffffffu, s, o);
    if (lane == 0) red[h][wid] = s;
  }
  __syncthreads();
  if (tid < 6){
    float ss = red[tid][0];
    #pragma unroll
    for (int i=1;i<8;i++) ss += red[tid][i];
    bcast[tid] = ss;
  }
  __syncthreads();
  #pragma unroll
  for (int h=0;h<6;h++){
    float inv = 1.0f / bcast[h];
    size_t base = ((size_t)(b*6+h) << 20) + ((size_t)n << 10) + tid;
    #pragma unroll
    for (int j=0;j<4;j++){
      at[h][j] *= inv;
      am_out[base + 256*j] = at[h][j];
    }
  }
  // conv + tanh + gumbel mask
  #pragma unroll
  for (int o=0;o<6;o++){
    #pragma unroll
    for (int j=0;j<4;j++){
      float t = scb[o];
      #pragma unroll
      for (int h=0;h<6;h++) t = fmaf(scw[o*6+h], qv[h][j], t);
      float u = (tanhf(t) + 1.0f) * 0.5f;
      unsigned idx = ((unsigned)(b*6+o) << 20) | ((unsigned)n << 10) | (unsigned)(tid + 256*j);
      u_out[idx] = u;
      unsigned a0,a1,b0,b1;
      threefry2x32(k0a,k0b, 0u, idx, a0,a1);
      threefry2x32(k1a,k1b, 0u, idx, b0,b1);
      float g0 = gumbel_from_bits(a0 ^ a1);
      float g1 = gumbel_from_bits(b0 ^ b1);
      bool hard = ((1.0f - u) + g1) > (u + g0);
      float masked = hard ? at[o][j] : 0.0f;
      __nv_bfloat16 mh, ml;
      f2bf(masked, mh, ml);
      g_ah[idx] = mh;
      g_al[idx] = ml;
    }
  }
}

// ---------------- K4: attn @ v via mma.sync bf16 split ----------------
__global__ __launch_bounds__(256) void k_attnv_mma(){
  __shared__ __align__(16) __nv_bfloat16 sAh[64*SQS], sAl[64*SQS];
  __shared__ __align__(16) __nv_bfloat16 sVh[64*SQS], sVl[64*SQS];
  const int tid = threadIdx.x;
  const int p = blockIdx.y, n0 = blockIdx.x*64;
  const __nv_bfloat16* Ah = g_ah + (((size_t)p<<10) + n0 << 10);
  const __nv_bfloat16* Al = g_al + (((size_t)p<<10) + n0 << 10);
  const __nv_bfloat16* Vh = g_vh + (size_t)p*PLANE_QV;
  const __nv_bfloat16* Vl = g_vl + (size_t)p*PLANE_QV;
  const int w = tid >> 5, lane = tid & 31;
  const int ns = (w >> 1) * 16, dh = (w & 1) * 32;
  float acc[4][4] = {};
  const int crow = tid >> 3, ccol = (tid & 7) * 8;   // copy assignment
  for (int mb = 0; mb < 1024; mb += 64){
    #pragma unroll
    for (int c0=0;c0<2;c0++){
      int row = crow + 32*c0;
      *(uint4*)&sAh[row*SQS+ccol] = *(const uint4*)&Ah[(size_t)row*1024 + mb + ccol];
      *(uint4*)&sAl[row*SQS+ccol] = *(const uint4*)&Al[(size_t)row*1024 + mb + ccol];
      *(uint4*)&sVh[row*SQS+ccol] = *(const uint4*)&Vh[(size_t)row*1024 + mb + ccol];
      *(uint4*)&sVl[row*SQS+ccol] = *(const uint4*)&Vl[(size_t)row*1024 + mb + ccol];
    }
    __syncthreads();
    #pragma unroll
    for (int ks=0; ks<4; ks++){
      const int k0 = ks*16;
      const int arow = ns + (lane & 15);
      const int acol = k0 + (lane >> 4) * 8;
      uint32_t ah0,ah1,ah2,ah3, al0,al1,al2,al3;
      ldm_x4(sptr(&sAh[arow*SQS + acol]), ah0,ah1,ah2,ah3);
      ldm_x4(sptr(&sAl[arow*SQS + acol]), al0,al1,al2,al3);
      const int bro = (lane & 7);
      const int bco = k0 + ((lane >> 3) & 1) * 8;
      #pragma unroll
      for (int t=0;t<4;t++){
        const int brow = dh + t*8 + bro;
        uint32_t bh0,bh1, bl0,bl1;
        ldm_x2(sptr(&sVh[brow*SQS + bco]), bh0,bh1);
        ldm_x2(sptr(&sVl[brow*SQS + bco]), bl0,bl1);
        mma16816(acc[t][0],acc[t][1],acc[t][2],acc[t][3], ah0,ah1,ah2,ah3, bh0,bh1);
        mma16816(acc[t][0],acc[t][1],acc[t][2],acc[t][3], ah0,ah1,ah2,ah3, bl0,bl1);
        mma16816(acc[t][0],acc[t][1],acc[t][2],acc[t][3], al0,al1,al2,al3, bh0,bh1);
      }
    }
    __syncthreads();
  }
  const int bb = p / 6, hh = p % 6;
  const int orow = n0 + ns + (lane >> 2);
  #pragma unroll
  for (int t=0;t<4;t++){
    const int ocol = hh*64 + dh + t*8 + (lane & 3)*2;
    size_t base = (size_t)(bb*NN + orow)*NCH + ocol;
    *(float2*)&g_o[base]         = make_float2(acc[t][0], acc[t][1]);
    *(float2*)&g_o[base + 8*NCH] = make_float2(acc[t][2], acc[t][3]);
  }
}

// ---------------- K5: out = g_o @ proj_w + proj_b ----------------
__global__ __launch_bounds__(256) void k_proj(const float* __restrict__ W,
                                              const float* __restrict__ bias,
                                              float* __restrict__ out){
  __shared__ __align__(16) float sA[16][68];
  __shared__ __align__(16) float sB[16][64];
  const int tid = threadIdx.x;
  const int tx = tid & 15, ty = tid >> 4;
  const int n0 = blockIdx.x * 64;
  const int m0 = blockIdx.y * 64;
  float acc[4][4] = {};
  const int lak = tid & 15;
  const int lam = (tid >> 4) * 4;
  const int lbn = tid & 63;
  const int lbk = (tid >> 6) * 4;
  for (int kb = 0; kb < 384; kb += 16){
    #pragma unroll
    for (int i=0;i<4;i++) sA[lak][lam+i] = g_o[(size_t)(m0+lam+i)*384 + kb + lak];
    #pragma unroll
    for (int i=0;i<4;i++) sB[lbk+i][lbn] = W[(size_t)(kb+lbk+i)*384 + n0 + lbn];
    __syncthreads();
    #pragma unroll
    for (int kk=0;kk<16;kk++){
      float4 av = *(const float4*)&sA[kk][ty*4];
      float4 bv = *(const float4*)&sB[kk][tx*4];
      OUTER4(av,bv,acc)
    }
    __syncthreads();
  }
  const float b0 = bias[n0 + tx*4 + 0];
  const float b1 = bias[n0 + tx*4 + 1];
  const float b2 = bias[n0 + tx*4 + 2];
  const float b3 = bias[n0 + tx*4 + 3];
  #pragma unroll
  for (int i=0;i<4;i++){
    int r = m0 + ty*4 + i;
    float4 v = make_float4(acc[i][0]+b0, acc[i][1]+b1, acc[i][2]+b2, acc[i][3]+b3);
    *(float4*)&out[(size_t)r*384 + n0 + tx*4] = v;
  }
}

// ---------------- launch ----------------
extern "C" void kernel_launch(void* const* d_in, const int* in_sizes, int n_in,
                              void* d_out, int out_size){
  (void)in_sizes; (void)n_in; (void)out_size;
  const float* x      = (const float*)d_in[0];
  const float* qkv_w  = (const float*)d_in[1];
  const float* qkv_b  = (const float*)d_in[2];
  const float* proj_w = (const float*)d_in[3];
  const float* proj_b = (const float*)d_in[4];
  const float* conv_w = (const float*)d_in[5];
  const float* conv_b = (const float*)d_in[6];
  float* out      = (float*)d_out;
  float* out_attn = out + (size_t)NB*NN*NCH;          // 1,572,864
  float* out_u    = out_attn + (size_t)S_TOTAL;       // +25,165,824

  unsigned k0a,k0b,k1a,k1b;
  threefry2x32(0u, 42u, 0u, 0u, k0a, k0b);
  threefry2x32(0u, 42u, 0u, 1u, k1a, k1b);

  k_qkv       <<<dim3(18,64),   256>>>(x, qkv_w, qkv_b);
  k_scores_mma<<<dim3(16,16,24),256>>>();
  k_smix      <<<dim3(1024,4),  256>>>(conv_w, conv_b, out_attn, out_u, k0a,k0b,k1a,k1b);
  k_attnv_mma <<<dim3(16,24),   256>>>();
  k_proj      <<<dim3(6,64),    256>>>(proj_w, proj_b, out);
}